// round 5
// baseline (speedup 1.0000x reference)
#include <cuda_runtime.h>
#include <math.h>

#define BATCH 8192
#define NHS   64
#define NC    68   // HS + 4 channels

typedef unsigned long long ull;

// ---------------- scratch (device globals: no allocation allowed) ----------
__device__ float g_x[BATCH * NHS * 36];            // current x, (B,64,6,6)
__device__ float g_vec[4 * BATCH * NC * 25];       // conv output vectors
__device__ float g_mat[4 * BATCH * NHS];           // final matmul result

// ---------------- f32x2 packed helpers --------------------------------------
__device__ __forceinline__ ull ffma2(ull a, ull b, ull c) {
    ull d;
    asm("fma.rn.f32x2 %0, %1, %2, %3;" : "=l"(d) : "l"(a), "l"(b), "l"(c));
    return d;
}
__device__ __forceinline__ void unpack2(ull v, float& lo, float& hi) {
    asm("mov.b64 {%0, %1}, %2;" : "=f"(lo), "=f"(hi) : "l"(v));
}

__device__ __forceinline__ float sc_act(float v) {
    return __sinf(v) + __cosf(v);
}

// ---------------- conv core: one 3x3 SAME conv, ci-paired f32x2 -------------
// Thread owns (co, slot); acc2[p] holds (even-ci partial, odd-ci partial).
// Inputs in shared as [p][ci] (LDS.64 -> ci pair), weights staged as ci pairs.
template<int WS>
__device__ __forceinline__ void conv_core(
    ull* acc2, const float* __restrict__ wg,
    float* sh_w, const float* tin, int co, int tid)
{
    constexpr int P = WS * WS;
    #pragma unroll 1
    for (int chunk = 0; chunk < 17; chunk++) {
        __syncthreads();
        // stage w pairs: layout [co(68)][cip(2)][k(9)][pc(2)] = 2448 floats
        #pragma unroll
        for (int i = 0; i < 9; i++) {
            const int e  = tid + i * 272;
            const int pc = e & 1;
            const int t  = e >> 1;
            const int k  = t % 9;
            const int t2 = t / 9;
            const int cip = t2 & 1;
            const int c   = t2 >> 1;
            sh_w[e] = wg[c * 612 + (chunk * 4 + cip * 2 + pc) * 9 + k];
        }
        __syncthreads();
        #pragma unroll
        for (int cip = 0; cip < 2; cip++) {
            const int cib = chunk * 4 + cip * 2;
            ull wv[9];
            #pragma unroll
            for (int k = 0; k < 9; k++)
                wv[k] = *(const ull*)&sh_w[((co * 2 + cip) * 9 + k) * 2];
            #pragma unroll
            for (int ry = 0; ry < WS; ry++) {
                ull rrow[WS];
                #pragma unroll
                for (int x = 0; x < WS; x++)
                    rrow[x] = *(const ull*)&tin[(ry * WS + x) * NC + cib];
                #pragma unroll
                for (int ky = -1; ky <= 1; ky++) {
                    const int y = ry - ky;
                    if (y < 0 || y >= WS) continue;
                    #pragma unroll
                    for (int x = 0; x < WS; x++) {
                        ull a = acc2[y * WS + x];
                        #pragma unroll
                        for (int kx = -1; kx <= 1; kx++) {
                            const int xx = x + kx;
                            if (xx < 0 || xx >= WS) continue;
                            a = ffma2(wv[(ky + 1) * 3 + (kx + 1)], rrow[xx], a);
                        }
                        acc2[y * WS + x] = a;
                    }
                }
            }
        }
    }
}

// ---------------- fused per-iteration conv pipeline -------------------------
// One CTA = 4 (corner,batch) tiles. 272 threads: co = tid>>2 (0..67), slot = tid&3.
template<int WS, bool FIRST>
__global__ void __launch_bounds__(272, 2) conv_pipe(
    const float* __restrict__ xin,
    const float* __restrict__ cell,
    const float* __restrict__ coord,
    const float* __restrict__ w1, const float* __restrict__ b1,
    const float* __restrict__ w3, const float* __restrict__ b3)
{
    constexpr int P   = WS * WS;
    constexpr int OFF = 6 - WS;
    extern __shared__ float sh[];
    float* sh_t = sh;               // [4][P][NC]
    float* sh_w = sh + 4 * P * NC;  // 2448 floats

    const int tid   = threadIdx.x;
    const int slot  = tid & 3;
    const int co    = tid >> 2;
    const int tile0 = blockIdx.x * 4;

    // corner-extract + concat(x,cell,coord) + sin+cos into [slot][p][ci]
    for (int e = tid; e < 4 * NC * P; e += 272) {
        const int s  = e / (NC * P);
        const int rr = e % (NC * P);
        const int p  = rr / NC, ch = rr % NC;
        const int y  = p / WS, xp = p % WS;
        const int tile = tile0 + s;
        const int c = tile >> 13, b = tile & (BATCH - 1);
        const int Y = y + (c >> 1) * OFF, X = xp + (c & 1) * OFF;
        float v;
        if (ch < NHS)
            v = FIRST ? xin[((b * NHS + ch) * 6 + Y) * 6 + X]
                      : g_x[((b * NHS + ch) * 6 + Y) * 6 + X];
        else if (ch < 66)
            v = cell[b * 2 + (ch - NHS)];
        else
            v = coord[((b * 2 + (ch - 66)) * 6 + Y) * 6 + X];
        sh_t[s * (NC * P) + rr] = sc_act(v);
    }
    // conv_core's leading __syncthreads orders staging before reads

    float* tin = sh_t + slot * (NC * P);

    ull acc2[P];
    #pragma unroll
    for (int p = 0; p < P; p++) acc2[p] = 0ull;
    conv_core<WS>(acc2, w1, sh_w, tin, co, tid);

    // bias + relu + act, write back into [p][co] layout (sync: others may read)
    __syncthreads();
    {
        const float bb = b1[co];
        #pragma unroll
        for (int p = 0; p < P; p++) {
            float lo, hi;
            unpack2(acc2[p], lo, hi);
            tin[p * NC + co] = sc_act(fmaxf(lo + hi + bb, 0.f));
            acc2[p] = 0ull;
        }
    }
    // conv_core's leading __syncthreads orders these writes before reads
    conv_core<WS>(acc2, w3, sh_w, tin, co, tid);

    const float bb3 = b3[co];
    float* outp = g_vec + (size_t)(tile0 + slot) * (NC * P) + co * P;
    #pragma unroll
    for (int p = 0; p < P; p++) {
        float lo, hi;
        unpack2(acc2[p], lo, hi);
        outp[p] = fmaxf(lo + hi + bb3, 0.f);
    }
}

// ---------------- f32x2 SGEMM: 128x128 block, 8x8 microtile -----------------
// As: m-pairs (LDS.64). Bs stored duplicated so b-broadcast pair = one LDS.64.
// Register double-buffer on the global k-tiles.
// MODE 0: +bias, relu, scatter into g_x. MODE 1: +bias -> g_mat.
template<int MODE>
__global__ void __launch_bounds__(256, 2) sgemm2(
    const float* __restrict__ Wt,
    const float* __restrict__ bias,
    int K, int Ntot)
{
    __shared__ float As[16][128];
    __shared__ float Bs[16][256];   // duplicated pairs
    const int tid = threadIdx.x;
    const int tx  = tid & 15;        // n direction (n = tx + j*16)
    const int ty  = tid >> 4;        // m direction (m = ty*8 + 0..7)
    const int n0  = blockIdx.x * 128;
    const int m0  = blockIdx.y * 128;
    const float* A = g_vec;

    ull acc[4][8];
    #pragma unroll
    for (int ip = 0; ip < 4; ip++)
        #pragma unroll
        for (int j = 0; j < 8; j++) acc[ip][j] = 0ull;

    float4 va[2], vb[2];
    const int lrow = tid >> 2, lkq = tid & 3;

    // prefetch k0 = 0
    #pragma unroll
    for (int i = 0; i < 2; i++) {
        const int r  = lrow + 64 * i;
        const int kg = lkq * 4;
        va[i] = make_float4(0.f, 0.f, 0.f, 0.f);
        vb[i] = va[i];
        if (kg < K) {
            va[i] = *(const float4*)&A[(size_t)(m0 + r) * K + kg];
            if (n0 + r < Ntot)
                vb[i] = *(const float4*)&Wt[(size_t)(n0 + r) * K + kg];
        }
    }

    for (int k0 = 0; k0 < K; k0 += 16) {
        #pragma unroll
        for (int i = 0; i < 2; i++) {
            const int r = lrow + 64 * i;
            As[lkq * 4 + 0][r] = va[i].x;
            As[lkq * 4 + 1][r] = va[i].y;
            As[lkq * 4 + 2][r] = va[i].z;
            As[lkq * 4 + 3][r] = va[i].w;
            Bs[lkq * 4 + 0][2 * r] = vb[i].x; Bs[lkq * 4 + 0][2 * r + 1] = vb[i].x;
            Bs[lkq * 4 + 1][2 * r] = vb[i].y; Bs[lkq * 4 + 1][2 * r + 1] = vb[i].y;
            Bs[lkq * 4 + 2][2 * r] = vb[i].z; Bs[lkq * 4 + 2][2 * r + 1] = vb[i].z;
            Bs[lkq * 4 + 3][2 * r] = vb[i].w; Bs[lkq * 4 + 3][2 * r + 1] = vb[i].w;
        }
        __syncthreads();

        // prefetch next k-tile
        if (k0 + 16 < K) {
            #pragma unroll
            for (int i = 0; i < 2; i++) {
                const int r  = lrow + 64 * i;
                const int kg = k0 + 16 + lkq * 4;
                va[i] = make_float4(0.f, 0.f, 0.f, 0.f);
                vb[i] = va[i];
                if (kg < K) {
                    va[i] = *(const float4*)&A[(size_t)(m0 + r) * K + kg];
                    if (n0 + r < Ntot)
                        vb[i] = *(const float4*)&Wt[(size_t)(n0 + r) * K + kg];
                }
            }
        }

        #pragma unroll
        for (int kk = 0; kk < 16; kk++) {
            ull a[4], b2[8];
            #pragma unroll
            for (int ip = 0; ip < 4; ip++)
                a[ip] = *(const ull*)&As[kk][ty * 8 + ip * 2];
            #pragma unroll
            for (int j = 0; j < 8; j++)
                b2[j] = *(const ull*)&Bs[kk][2 * (tx + j * 16)];
            #pragma unroll
            for (int ip = 0; ip < 4; ip++)
                #pragma unroll
                for (int j = 0; j < 8; j++)
                    acc[ip][j] = ffma2(a[ip], b2[j], acc[ip][j]);
        }
        __syncthreads();
    }

    #pragma unroll
    for (int j = 0; j < 8; j++) {
        const int n = n0 + tx + j * 16;
        if (n >= Ntot) continue;
        const float bb = bias[n];
        #pragma unroll
        for (int ip = 0; ip < 4; ip++) {
            float lo, hi;
            unpack2(acc[ip][j], lo, hi);
            const int m = m0 + ty * 8 + ip * 2;
            if (MODE == 0) {
                const int h = n / 9, r = (n % 9) / 3, cc = n % 3;
                {
                    const int c = m >> 13, b = m & (BATCH - 1);
                    g_x[((b * NHS + h) * 6 + r + 3 * (c >> 1)) * 6 + cc + 3 * (c & 1)]
                        = fmaxf(lo + bb, 0.f);
                }
                {
                    const int m1 = m + 1;
                    const int c = m1 >> 13, b = m1 & (BATCH - 1);
                    g_x[((b * NHS + h) * 6 + r + 3 * (c >> 1)) * 6 + cc + 3 * (c & 1)]
                        = fmaxf(hi + bb, 0.f);
                }
            } else {
                g_mat[m * NHS + n]       = lo + bb;
                g_mat[(m + 1) * NHS + n] = hi + bb;
            }
        }
    }
}

// gather the 4 exact 3x3 quadrants of x into g_vec rows of length 576
__global__ void extract_final_kernel() {
    const int idx = blockIdx.x * blockDim.x + threadIdx.x;
    if (idx >= 4 * BATCH * 576) return;
    const int m = idx / 576, k = idx % 576;
    const int c = m >> 13, b = m & (BATCH - 1);
    const int ch = k / 9, r = (k % 9) / 3, cc = k % 3;
    g_vec[idx] = g_x[((b * NHS + ch) * 6 + r + 3 * (c >> 1)) * 6 + cc + 3 * (c & 1)];
}

// out = x_center * g_mat (flat reinterpretation of the (4B,64)->(B,64,2,2) reshape)
__global__ void final_mul_kernel(float* __restrict__ out) {
    const int idx = blockIdx.x * blockDim.x + threadIdx.x;
    if (idx >= BATCH * NHS * 4) return;
    const int b = idx >> 8, rest = idx & 255;
    const int h = rest >> 2, ij = rest & 3;
    const float xc = g_x[((b * NHS + h) * 6 + 2 + (ij >> 1)) * 6 + 2 + (ij & 1)];
    out[idx] = xc * g_mat[idx];
}

extern "C" void kernel_launch(void* const* d_in, const int* in_sizes, int n_in,
                              void* d_out, int out_size)
{
    const float* x     = (const float*)d_in[0];
    const float* cell  = (const float*)d_in[1];
    const float* coord = (const float*)d_in[2];
    const float* c1w   = (const float*)d_in[3];
    const float* c1b   = (const float*)d_in[4];
    const float* c3w   = (const float*)d_in[5];
    const float* c3b   = (const float*)d_in[6];
    const float* l5w   = (const float*)d_in[7];
    const float* l5b   = (const float*)d_in[8];
    const float* l4w   = (const float*)d_in[9];
    const float* l4b   = (const float*)d_in[10];
    const float* l3w   = (const float*)d_in[11];
    const float* l3b   = (const float*)d_in[12];
    const float* fw    = (const float*)d_in[13];
    const float* fb    = (const float*)d_in[14];
    float* out = (float*)d_out;

    const int NCONV = BATCH * 4 / 4;   // 8192 CTAs
    const int sh5 = (4 * 25 * NC + 2448) * 4;
    const int sh4 = (4 * 16 * NC + 2448) * 4;
    const int sh3 = (4 *  9 * NC + 2448) * 4;

    // ws = 5
    conv_pipe<5, true ><<<NCONV, 272, sh5>>>(x, cell, coord, c1w, c1b, c3w, c3b);
    sgemm2<0><<<dim3(5, 256), 256>>>(l5w, l5b, NC * 25, 576);
    // ws = 4
    conv_pipe<4, false><<<NCONV, 272, sh4>>>(x, cell, coord, c1w, c1b, c3w, c3b);
    sgemm2<0><<<dim3(5, 256), 256>>>(l4w, l4b, NC * 16, 576);
    // ws = 3
    conv_pipe<3, false><<<NCONV, 272, sh3>>>(x, cell, coord, c1w, c1b, c3w, c3b);
    sgemm2<0><<<dim3(5, 256), 256>>>(l3w, l3b, NC * 9, 576);
    // final
    extract_final_kernel<<<(4 * BATCH * 576 + 255) / 256, 256>>>();
    sgemm2<1><<<dim3(1, 256), 256>>>(fw, fb, 576, NHS);
    final_mul_kernel<<<(BATCH * NHS * 4 + 255) / 256, 256>>>(out);
}

// round 6
// speedup vs baseline: 1.0010x; 1.0010x over previous
#include <cuda_runtime.h>
#include <math.h>

#define BATCH 8192
#define NHS   64
#define NC    68   // HS + 4 channels

typedef unsigned long long ull;

// ---------------- scratch (device globals: no allocation allowed) ----------
__device__ float g_x[BATCH * NHS * 36];            // current x, (B,64,6,6)
__device__ float g_vec[4 * BATCH * NC * 25];       // conv output vectors
__device__ float g_mat[4 * BATCH * NHS];           // final matmul result

// ---------------- f32x2 packed helpers --------------------------------------
__device__ __forceinline__ ull ffma2(ull a, ull b, ull c) {
    ull d;
    asm("fma.rn.f32x2 %0, %1, %2, %3;" : "=l"(d) : "l"(a), "l"(b), "l"(c));
    return d;
}
__device__ __forceinline__ void unpack2(ull v, float& lo, float& hi) {
    asm("mov.b64 {%0, %1}, %2;" : "=f"(lo), "=f"(hi) : "l"(v));
}

__device__ __forceinline__ float sc_act(float v) {
    return __sinf(v) + __cosf(v);
}

// ---------------- conv core: one 3x3 SAME conv, ci-paired f32x2 -------------
// Thread owns (co, slot); acc2[p] holds (even-ci partial, odd-ci partial).
// Inputs in shared as [p][ci] (LDS.64 -> ci pair), weights staged as ci pairs.
template<int WS>
__device__ __forceinline__ void conv_core(
    ull* acc2, const float* __restrict__ wg,
    float* sh_w, const float* tin, int co, int tid)
{
    constexpr int P = WS * WS;
    #pragma unroll 1
    for (int chunk = 0; chunk < 17; chunk++) {
        __syncthreads();
        // stage w pairs: layout [co(68)][cip(2)][k(9)][pc(2)] = 2448 floats
        #pragma unroll
        for (int i = 0; i < 9; i++) {
            const int e  = tid + i * 272;
            const int pc = e & 1;
            const int t  = e >> 1;
            const int k  = t % 9;
            const int t2 = t / 9;
            const int cip = t2 & 1;
            const int c   = t2 >> 1;
            sh_w[e] = wg[c * 612 + (chunk * 4 + cip * 2 + pc) * 9 + k];
        }
        __syncthreads();
        #pragma unroll
        for (int cip = 0; cip < 2; cip++) {
            const int cib = chunk * 4 + cip * 2;
            ull wv[9];
            #pragma unroll
            for (int k = 0; k < 9; k++)
                wv[k] = *(const ull*)&sh_w[((co * 2 + cip) * 9 + k) * 2];
            #pragma unroll
            for (int ry = 0; ry < WS; ry++) {
                ull rrow[WS];
                #pragma unroll
                for (int x = 0; x < WS; x++)
                    rrow[x] = *(const ull*)&tin[(ry * WS + x) * NC + cib];
                #pragma unroll
                for (int ky = -1; ky <= 1; ky++) {
                    const int y = ry - ky;
                    if (y < 0 || y >= WS) continue;
                    #pragma unroll
                    for (int x = 0; x < WS; x++) {
                        ull a = acc2[y * WS + x];
                        #pragma unroll
                        for (int kx = -1; kx <= 1; kx++) {
                            const int xx = x + kx;
                            if (xx < 0 || xx >= WS) continue;
                            a = ffma2(wv[(ky + 1) * 3 + (kx + 1)], rrow[xx], a);
                        }
                        acc2[y * WS + x] = a;
                    }
                }
            }
        }
    }
}

// ---------------- fused per-iteration conv pipeline -------------------------
// One CTA = 4 (corner,batch) tiles. 272 threads: co = tid>>2 (0..67), slot = tid&3.
template<int WS, bool FIRST>
__global__ void __launch_bounds__(272, 2) conv_pipe(
    const float* __restrict__ xin,
    const float* __restrict__ cell,
    const float* __restrict__ coord,
    const float* __restrict__ w1, const float* __restrict__ b1,
    const float* __restrict__ w3, const float* __restrict__ b3)
{
    constexpr int P   = WS * WS;
    constexpr int OFF = 6 - WS;
    extern __shared__ float sh[];
    float* sh_t = sh;               // [4][P][NC]
    float* sh_w = sh + 4 * P * NC;  // 2448 floats

    const int tid   = threadIdx.x;
    const int slot  = tid & 3;
    const int co    = tid >> 2;
    const int tile0 = blockIdx.x * 4;

    // corner-extract + concat(x,cell,coord) + sin+cos into [slot][p][ci]
    for (int e = tid; e < 4 * NC * P; e += 272) {
        const int s  = e / (NC * P);
        const int rr = e % (NC * P);
        const int p  = rr / NC, ch = rr % NC;
        const int y  = p / WS, xp = p % WS;
        const int tile = tile0 + s;
        const int c = tile >> 13, b = tile & (BATCH - 1);
        const int Y = y + (c >> 1) * OFF, X = xp + (c & 1) * OFF;
        float v;
        if (ch < NHS)
            v = FIRST ? xin[((b * NHS + ch) * 6 + Y) * 6 + X]
                      : g_x[((b * NHS + ch) * 6 + Y) * 6 + X];
        else if (ch < 66)
            v = cell[b * 2 + (ch - NHS)];
        else
            v = coord[((b * 2 + (ch - 66)) * 6 + Y) * 6 + X];
        sh_t[s * (NC * P) + rr] = sc_act(v);
    }
    // conv_core's leading __syncthreads orders staging before reads

    float* tin = sh_t + slot * (NC * P);

    ull acc2[P];
    #pragma unroll
    for (int p = 0; p < P; p++) acc2[p] = 0ull;
    conv_core<WS>(acc2, w1, sh_w, tin, co, tid);

    // bias + relu + act, write back into [p][co] layout (sync: others may read)
    __syncthreads();
    {
        const float bb = b1[co];
        #pragma unroll
        for (int p = 0; p < P; p++) {
            float lo, hi;
            unpack2(acc2[p], lo, hi);
            tin[p * NC + co] = sc_act(fmaxf(lo + hi + bb, 0.f));
            acc2[p] = 0ull;
        }
    }
    // conv_core's leading __syncthreads orders these writes before reads
    conv_core<WS>(acc2, w3, sh_w, tin, co, tid);

    const float bb3 = b3[co];
    float* outp = g_vec + (size_t)(tile0 + slot) * (NC * P) + co * P;
    #pragma unroll
    for (int p = 0; p < P; p++) {
        float lo, hi;
        unpack2(acc2[p], lo, hi);
        outp[p] = fmaxf(lo + hi + bb3, 0.f);
    }
}

// ---------------- f32x2 SGEMM: 128x128 block, 8x8 microtile -----------------
// As: m-pairs (LDS.64). Bs stored duplicated so b-broadcast pair = one LDS.64.
// Register double-buffer on the global k-tiles.
// MODE 0: +bias, relu, scatter into g_x. MODE 1: +bias -> g_mat.
template<int MODE>
__global__ void __launch_bounds__(256, 2) sgemm2(
    const float* __restrict__ Wt,
    const float* __restrict__ bias,
    int K, int Ntot)
{
    __shared__ float As[16][128];
    __shared__ float Bs[16][256];   // duplicated pairs
    const int tid = threadIdx.x;
    const int tx  = tid & 15;        // n direction (n = tx + j*16)
    const int ty  = tid >> 4;        // m direction (m = ty*8 + 0..7)
    const int n0  = blockIdx.x * 128;
    const int m0  = blockIdx.y * 128;
    const float* A = g_vec;

    ull acc[4][8];
    #pragma unroll
    for (int ip = 0; ip < 4; ip++)
        #pragma unroll
        for (int j = 0; j < 8; j++) acc[ip][j] = 0ull;

    float4 va[2], vb[2];
    const int lrow = tid >> 2, lkq = tid & 3;

    // prefetch k0 = 0
    #pragma unroll
    for (int i = 0; i < 2; i++) {
        const int r  = lrow + 64 * i;
        const int kg = lkq * 4;
        va[i] = make_float4(0.f, 0.f, 0.f, 0.f);
        vb[i] = va[i];
        if (kg < K) {
            va[i] = *(const float4*)&A[(size_t)(m0 + r) * K + kg];
            if (n0 + r < Ntot)
                vb[i] = *(const float4*)&Wt[(size_t)(n0 + r) * K + kg];
        }
    }

    for (int k0 = 0; k0 < K; k0 += 16) {
        #pragma unroll
        for (int i = 0; i < 2; i++) {
            const int r = lrow + 64 * i;
            As[lkq * 4 + 0][r] = va[i].x;
            As[lkq * 4 + 1][r] = va[i].y;
            As[lkq * 4 + 2][r] = va[i].z;
            As[lkq * 4 + 3][r] = va[i].w;
            Bs[lkq * 4 + 0][2 * r] = vb[i].x; Bs[lkq * 4 + 0][2 * r + 1] = vb[i].x;
            Bs[lkq * 4 + 1][2 * r] = vb[i].y; Bs[lkq * 4 + 1][2 * r + 1] = vb[i].y;
            Bs[lkq * 4 + 2][2 * r] = vb[i].z; Bs[lkq * 4 + 2][2 * r + 1] = vb[i].z;
            Bs[lkq * 4 + 3][2 * r] = vb[i].w; Bs[lkq * 4 + 3][2 * r + 1] = vb[i].w;
        }
        __syncthreads();

        // prefetch next k-tile
        if (k0 + 16 < K) {
            #pragma unroll
            for (int i = 0; i < 2; i++) {
                const int r  = lrow + 64 * i;
                const int kg = k0 + 16 + lkq * 4;
                va[i] = make_float4(0.f, 0.f, 0.f, 0.f);
                vb[i] = va[i];
                if (kg < K) {
                    va[i] = *(const float4*)&A[(size_t)(m0 + r) * K + kg];
                    if (n0 + r < Ntot)
                        vb[i] = *(const float4*)&Wt[(size_t)(n0 + r) * K + kg];
                }
            }
        }

        #pragma unroll
        for (int kk = 0; kk < 16; kk++) {
            ull a[4], b2[8];
            #pragma unroll
            for (int ip = 0; ip < 4; ip++)
                a[ip] = *(const ull*)&As[kk][ty * 8 + ip * 2];
            #pragma unroll
            for (int j = 0; j < 8; j++)
                b2[j] = *(const ull*)&Bs[kk][2 * (tx + j * 16)];
            #pragma unroll
            for (int ip = 0; ip < 4; ip++)
                #pragma unroll
                for (int j = 0; j < 8; j++)
                    acc[ip][j] = ffma2(a[ip], b2[j], acc[ip][j]);
        }
        __syncthreads();
    }

    #pragma unroll
    for (int j = 0; j < 8; j++) {
        const int n = n0 + tx + j * 16;
        if (n >= Ntot) continue;
        const float bb = bias[n];
        #pragma unroll
        for (int ip = 0; ip < 4; ip++) {
            float lo, hi;
            unpack2(acc[ip][j], lo, hi);
            const int m = m0 + ty * 8 + ip * 2;
            if (MODE == 0) {
                const int h = n / 9, r = (n % 9) / 3, cc = n % 3;
                {
                    const int c = m >> 13, b = m & (BATCH - 1);
                    g_x[((b * NHS + h) * 6 + r + 3 * (c >> 1)) * 6 + cc + 3 * (c & 1)]
                        = fmaxf(lo + bb, 0.f);
                }
                {
                    const int m1 = m + 1;
                    const int c = m1 >> 13, b = m1 & (BATCH - 1);
                    g_x[((b * NHS + h) * 6 + r + 3 * (c >> 1)) * 6 + cc + 3 * (c & 1)]
                        = fmaxf(hi + bb, 0.f);
                }
            } else {
                g_mat[m * NHS + n]       = lo + bb;
                g_mat[(m + 1) * NHS + n] = hi + bb;
            }
        }
    }
}

// gather the 4 exact 3x3 quadrants of x into g_vec rows of length 576
__global__ void extract_final_kernel() {
    const int idx = blockIdx.x * blockDim.x + threadIdx.x;
    if (idx >= 4 * BATCH * 576) return;
    const int m = idx / 576, k = idx % 576;
    const int c = m >> 13, b = m & (BATCH - 1);
    const int ch = k / 9, r = (k % 9) / 3, cc = k % 3;
    g_vec[idx] = g_x[((b * NHS + ch) * 6 + r + 3 * (c >> 1)) * 6 + cc + 3 * (c & 1)];
}

// out = x_center * g_mat (flat reinterpretation of the (4B,64)->(B,64,2,2) reshape)
__global__ void final_mul_kernel(float* __restrict__ out) {
    const int idx = blockIdx.x * blockDim.x + threadIdx.x;
    if (idx >= BATCH * NHS * 4) return;
    const int b = idx >> 8, rest = idx & 255;
    const int h = rest >> 2, ij = rest & 3;
    const float xc = g_x[((b * NHS + h) * 6 + 2 + (ij >> 1)) * 6 + 2 + (ij & 1)];
    out[idx] = xc * g_mat[idx];
}

extern "C" void kernel_launch(void* const* d_in, const int* in_sizes, int n_in,
                              void* d_out, int out_size)
{
    const float* x     = (const float*)d_in[0];
    const float* cell  = (const float*)d_in[1];
    const float* coord = (const float*)d_in[2];
    const float* c1w   = (const float*)d_in[3];
    const float* c1b   = (const float*)d_in[4];
    const float* c3w   = (const float*)d_in[5];
    const float* c3b   = (const float*)d_in[6];
    const float* l5w   = (const float*)d_in[7];
    const float* l5b   = (const float*)d_in[8];
    const float* l4w   = (const float*)d_in[9];
    const float* l4b   = (const float*)d_in[10];
    const float* l3w   = (const float*)d_in[11];
    const float* l3b   = (const float*)d_in[12];
    const float* fw    = (const float*)d_in[13];
    const float* fb    = (const float*)d_in[14];
    float* out = (float*)d_out;

    const int NCONV = BATCH * 4 / 4;   // 8192 CTAs
    const int sh5 = (4 * 25 * NC + 2448) * 4;
    const int sh4 = (4 * 16 * NC + 2448) * 4;
    const int sh3 = (4 *  9 * NC + 2448) * 4;

    // ws = 5
    conv_pipe<5, true ><<<NCONV, 272, sh5>>>(x, cell, coord, c1w, c1b, c3w, c3b);
    sgemm2<0><<<dim3(5, 256), 256>>>(l5w, l5b, NC * 25, 576);
    // ws = 4
    conv_pipe<4, false><<<NCONV, 272, sh4>>>(x, cell, coord, c1w, c1b, c3w, c3b);
    sgemm2<0><<<dim3(5, 256), 256>>>(l4w, l4b, NC * 16, 576);
    // ws = 3
    conv_pipe<3, false><<<NCONV, 272, sh3>>>(x, cell, coord, c1w, c1b, c3w, c3b);
    sgemm2<0><<<dim3(5, 256), 256>>>(l3w, l3b, NC * 9, 576);
    // final
    extract_final_kernel<<<(4 * BATCH * 576 + 255) / 256, 256>>>();
    sgemm2<1><<<dim3(1, 256), 256>>>(fw, fb, 576, NHS);
    final_mul_kernel<<<(BATCH * NHS * 4 + 255) / 256, 256>>>(out);
}

// round 11
// speedup vs baseline: 1.1073x; 1.1062x over previous
#include <cuda_runtime.h>
#include <math.h>

#define BATCH 8192
#define NHS   64
#define NC    68   // HS + 4 channels

typedef unsigned long long ull;

// ---------------- scratch (device globals: no allocation allowed) ----------
__device__ float g_x[BATCH * NHS * 36];            // current x, (B,64,6,6)
__device__ float g_vec[4 * BATCH * NC * 25];       // conv output vectors
__device__ float g_mat[4 * BATCH * NHS];           // final matmul result
__device__ float g_wp[2 * 9 * 4896];               // prepped conv weights

// ---------------- f32x2 packed helpers --------------------------------------
__device__ __forceinline__ ull ffma2(ull a, ull b, ull c) {
    ull d;
    asm("fma.rn.f32x2 %0, %1, %2, %3;" : "=l"(d) : "l"(a), "l"(b), "l"(c));
    return d;
}
__device__ __forceinline__ void unpack2(ull v, float& lo, float& hi) {
    asm("mov.b64 {%0, %1}, %2;" : "=f"(lo), "=f"(hi) : "l"(v));
}

__device__ __forceinline__ float sc_act(float v) {
    return __sinf(v) + __cosf(v);
}

__device__ __forceinline__ void cp_async8(float* dst_smem, const float* src) {
    const unsigned d = (unsigned)__cvta_generic_to_shared(dst_smem);
    asm volatile("cp.async.ca.shared.global [%0], [%1], 8;" :: "r"(d), "l"(src));
}

// ---------------- weight prep: reorder into per-chunk staging layout --------
// dst[conv][chunk][e], e = [co(68)][cip(4)][k(9)][pc(2)], ci = chunk*8+cip*2+pc
__global__ void prep_w(const float* __restrict__ w1, const float* __restrict__ w3) {
    const int idx = blockIdx.x * blockDim.x + threadIdx.x;
    if (idx >= 2 * 9 * 4896) return;
    const int conv  = idx / (9 * 4896);
    const int r     = idx % (9 * 4896);
    const int chunk = r / 4896, e = r % 4896;
    const int pc = e & 1;
    const int t  = e >> 1;
    const int k  = t % 9;
    const int cip = (t / 9) & 3;
    const int co  = t / 36;
    const int ci  = chunk * 8 + cip * 2 + pc;
    const float* w = conv ? w3 : w1;
    g_wp[idx] = (ci < NC) ? w[co * 612 + ci * 9 + k] : 0.f;
}

// ---------------- conv core: one 3x3 SAME conv, ci-paired f32x2 -------------
// Weights double-buffered via cp.async, ONE barrier per chunk.
template<int WS>
__device__ __forceinline__ void conv_core(
    ull* acc2, const float* __restrict__ wgp,   // 9*4896 prepped
    float* sh_w,                                // 2*4896
    const float* tin, int co, int tid)
{
    constexpr int P = WS * WS;
    // issue chunk 0 -> buf 0
    #pragma unroll
    for (int i = 0; i < 9; i++)
        cp_async8(&sh_w[(tid + i * 272) * 2], &wgp[(tid + i * 272) * 2]);
    asm volatile("cp.async.commit_group;");

    int buf = 0;
    #pragma unroll 1
    for (int chunk = 0; chunk < 9; chunk++) {
        asm volatile("cp.async.wait_group 0;");
        __syncthreads();
        if (chunk + 1 < 9) {
            const float* src = wgp + (chunk + 1) * 4896;
            float* dst = sh_w + (buf ^ 1) * 4896;
            #pragma unroll
            for (int i = 0; i < 9; i++)
                cp_async8(&dst[(tid + i * 272) * 2], &src[(tid + i * 272) * 2]);
            asm volatile("cp.async.commit_group;");
        }
        const float* wb = sh_w + buf * 4896;
        #pragma unroll
        for (int cip = 0; cip < 4; cip++) {
            const int cib = chunk * 8 + cip * 2;
            ull wv[9];
            #pragma unroll
            for (int k = 0; k < 9; k++)
                wv[k] = *(const ull*)&wb[((co * 4 + cip) * 9 + k) * 2];
            #pragma unroll
            for (int ry = 0; ry < WS; ry++) {
                ull rrow[WS];
                #pragma unroll
                for (int x = 0; x < WS; x++)
                    rrow[x] = *(const ull*)&tin[(ry * WS + x) * NC + cib];
                #pragma unroll
                for (int ky = -1; ky <= 1; ky++) {
                    const int y = ry - ky;
                    if (y < 0 || y >= WS) continue;
                    #pragma unroll
                    for (int x = 0; x < WS; x++) {
                        ull a = acc2[y * WS + x];
                        #pragma unroll
                        for (int kx = -1; kx <= 1; kx++) {
                            const int xx = x + kx;
                            if (xx < 0 || xx >= WS) continue;
                            a = ffma2(wv[(ky + 1) * 3 + (kx + 1)], rrow[xx], a);
                        }
                        acc2[y * WS + x] = a;
                    }
                }
            }
        }
        buf ^= 1;
    }
}

// ---------------- fused per-iteration conv pipeline -------------------------
// One CTA = 4 (corner,batch) tiles. 272 threads: co = tid>>2 (0..67), slot = tid&3.
template<int WS, bool FIRST>
__global__ void __launch_bounds__(272, 2) conv_pipe(
    const float* __restrict__ xin,
    const float* __restrict__ cell,
    const float* __restrict__ coord,
    const float* __restrict__ b1, const float* __restrict__ b3)
{
    constexpr int P    = WS * WS;
    constexpr int OFF  = 6 - WS;
    constexpr int TSTR = P * NC + 4;   // +4 zero pad (padded-ci overread target)
    extern __shared__ float sh[];
    float* sh_t = sh;                  // [4][TSTR]
    float* sh_w = sh + 4 * TSTR;       // 2*4896

    const int tid   = threadIdx.x;
    const int slot  = tid & 3;
    const int co    = tid >> 2;
    const int tile0 = blockIdx.x * 4;

    if (tid < 16)
        sh_t[(tid >> 2) * TSTR + P * NC + (tid & 3)] = 0.f;

    // corner-extract + concat + sin+cos. p-fastest order: coalesced LDG.
    for (int e = tid; e < 4 * NC * P; e += 272) {
        const int s  = e / (NC * P);
        const int r  = e % (NC * P);
        const int ch = r / P, p = r % P;
        const int y  = p / WS, xp = p % WS;
        const int tile = tile0 + s;
        const int c = tile >> 13, b = tile & (BATCH - 1);
        const int Y = y + (c >> 1) * OFF, X = xp + (c & 1) * OFF;
        float v;
        if (ch < NHS)
            v = FIRST ? xin[((b * NHS + ch) * 6 + Y) * 6 + X]
                      : g_x[((b * NHS + ch) * 6 + Y) * 6 + X];
        else if (ch < 66)
            v = cell[b * 2 + (ch - NHS)];
        else
            v = coord[((b * 2 + (ch - 66)) * 6 + Y) * 6 + X];
        sh_t[s * TSTR + p * NC + ch] = sc_act(v);
    }
    // conv_core's first (wait+)barrier orders tile staging before reads

    float* tin = sh_t + slot * TSTR;

    ull acc2[P];
    #pragma unroll
    for (int p = 0; p < P; p++) acc2[p] = 0ull;
    conv_core<WS>(acc2, g_wp, sh_w, tin, co, tid);

    // all conv1 reads of tin done before overwrite
    __syncthreads();
    {
        const float bb = b1[co];
        #pragma unroll
        for (int p = 0; p < P; p++) {
            float lo, hi;
            unpack2(acc2[p], lo, hi);
            tin[p * NC + co] = sc_act(fmaxf(lo + hi + bb, 0.f));
            acc2[p] = 0ull;
        }
    }
    // conv_core's chunk-0 barrier orders writeback before reads
    conv_core<WS>(acc2, g_wp + 9 * 4896, sh_w, tin, co, tid);

    const float bb3 = b3[co];
    float* outp = g_vec + (size_t)(tile0 + slot) * (NC * P) + co * P;
    #pragma unroll
    for (int p = 0; p < P; p++) {
        float lo, hi;
        unpack2(acc2[p], lo, hi);
        outp[p] = fmaxf(lo + hi + bb3, 0.f);
    }
}

// ---------------- f32x2 SGEMM: 128x128 block, 8x8 microtile -----------------
// As: m-pairs (LDS.64). Bs duplicated so b-broadcast pair = one LDS.64.
// MODE 0: +bias, relu, scatter into g_x. MODE 1: +bias -> g_mat.
template<int MODE>
__global__ void __launch_bounds__(256, 2) sgemm2(
    const float* __restrict__ Wt,
    const float* __restrict__ bias,
    int K, int Ntot)
{
    __shared__ float As[16][128];
    __shared__ float Bs[16][256];   // duplicated pairs
    const int tid = threadIdx.x;
    const int tx  = tid & 15;
    const int ty  = tid >> 4;
    const int n0  = blockIdx.x * 128;
    const int m0  = blockIdx.y * 128;
    const float* A = g_vec;

    ull acc[4][8];
    #pragma unroll
    for (int ip = 0; ip < 4; ip++)
        #pragma unroll
        for (int j = 0; j < 8; j++) acc[ip][j] = 0ull;

    float4 va[2], vb[2];
    const int lrow = tid >> 2, lkq = tid & 3;

    #pragma unroll
    for (int i = 0; i < 2; i++) {
        const int r  = lrow + 64 * i;
        const int kg = lkq * 4;
        va[i] = make_float4(0.f, 0.f, 0.f, 0.f);
        vb[i] = va[i];
        if (kg < K) {
            va[i] = *(const float4*)&A[(size_t)(m0 + r) * K + kg];
            if (n0 + r < Ntot)
                vb[i] = *(const float4*)&Wt[(size_t)(n0 + r) * K + kg];
        }
    }

    for (int k0 = 0; k0 < K; k0 += 16) {
        #pragma unroll
        for (int i = 0; i < 2; i++) {
            const int r = lrow + 64 * i;
            As[lkq * 4 + 0][r] = va[i].x;
            As[lkq * 4 + 1][r] = va[i].y;
            As[lkq * 4 + 2][r] = va[i].z;
            As[lkq * 4 + 3][r] = va[i].w;
            Bs[lkq * 4 + 0][2 * r] = vb[i].x; Bs[lkq * 4 + 0][2 * r + 1] = vb[i].x;
            Bs[lkq * 4 + 1][2 * r] = vb[i].y; Bs[lkq * 4 + 1][2 * r + 1] = vb[i].y;
            Bs[lkq * 4 + 2][2 * r] = vb[i].z; Bs[lkq * 4 + 2][2 * r + 1] = vb[i].z;
            Bs[lkq * 4 + 3][2 * r] = vb[i].w; Bs[lkq * 4 + 3][2 * r + 1] = vb[i].w;
        }
        __syncthreads();

        if (k0 + 16 < K) {
            #pragma unroll
            for (int i = 0; i < 2; i++) {
                const int r  = lrow + 64 * i;
                const int kg = k0 + 16 + lkq * 4;
                va[i] = make_float4(0.f, 0.f, 0.f, 0.f);
                vb[i] = va[i];
                if (kg < K) {
                    va[i] = *(const float4*)&A[(size_t)(m0 + r) * K + kg];
                    if (n0 + r < Ntot)
                        vb[i] = *(const float4*)&Wt[(size_t)(n0 + r) * K + kg];
                }
            }
        }

        #pragma unroll
        for (int kk = 0; kk < 16; kk++) {
            ull a[4], b2[8];
            #pragma unroll
            for (int ip = 0; ip < 4; ip++)
                a[ip] = *(const ull*)&As[kk][ty * 8 + ip * 2];
            #pragma unroll
            for (int j = 0; j < 8; j++)
                b2[j] = *(const ull*)&Bs[kk][2 * (tx + j * 16)];
            #pragma unroll
            for (int ip = 0; ip < 4; ip++)
                #pragma unroll
                for (int j = 0; j < 8; j++)
                    acc[ip][j] = ffma2(a[ip], b2[j], acc[ip][j]);
        }
        __syncthreads();
    }

    #pragma unroll
    for (int j = 0; j < 8; j++) {
        const int n = n0 + tx + j * 16;
        if (n >= Ntot) continue;
        const float bb = bias[n];
        #pragma unroll
        for (int ip = 0; ip < 4; ip++) {
            float lo, hi;
            unpack2(acc[ip][j], lo, hi);
            const int m = m0 + ty * 8 + ip * 2;
            if (MODE == 0) {
                const int h = n / 9, r = (n % 9) / 3, cc = n % 3;
                {
                    const int c = m >> 13, b = m & (BATCH - 1);
                    g_x[((b * NHS + h) * 6 + r + 3 * (c >> 1)) * 6 + cc + 3 * (c & 1)]
                        = fmaxf(lo + bb, 0.f);
                }
                {
                    const int m1 = m + 1;
                    const int c = m1 >> 13, b = m1 & (BATCH - 1);
                    g_x[((b * NHS + h) * 6 + r + 3 * (c >> 1)) * 6 + cc + 3 * (c & 1)]
                        = fmaxf(hi + bb, 0.f);
                }
            } else {
                g_mat[m * NHS + n]       = lo + bb;
                g_mat[(m + 1) * NHS + n] = hi + bb;
            }
        }
    }
}

// gather the 4 exact 3x3 quadrants of x into g_vec rows of length 576
__global__ void extract_final_kernel() {
    const int idx = blockIdx.x * blockDim.x + threadIdx.x;
    if (idx >= 4 * BATCH * 576) return;
    const int m = idx / 576, k = idx % 576;
    const int c = m >> 13, b = m & (BATCH - 1);
    const int ch = k / 9, r = (k % 9) / 3, cc = k % 3;
    g_vec[idx] = g_x[((b * NHS + ch) * 6 + r + 3 * (c >> 1)) * 6 + cc + 3 * (c & 1)];
}

// out = x_center * g_mat (flat reinterpretation of the (4B,64)->(B,64,2,2) reshape)
__global__ void final_mul_kernel(float* __restrict__ out) {
    const int idx = blockIdx.x * blockDim.x + threadIdx.x;
    if (idx >= BATCH * NHS * 4) return;
    const int b = idx >> 8, rest = idx & 255;
    const int h = rest >> 2, ij = rest & 3;
    const float xc = g_x[((b * NHS + h) * 6 + 2 + (ij >> 1)) * 6 + 2 + (ij & 1)];
    out[idx] = xc * g_mat[idx];
}

extern "C" void kernel_launch(void* const* d_in, const int* in_sizes, int n_in,
                              void* d_out, int out_size)
{
    const float* x     = (const float*)d_in[0];
    const float* cell  = (const float*)d_in[1];
    const float* coord = (const float*)d_in[2];
    const float* c1w   = (const float*)d_in[3];
    const float* c1b   = (const float*)d_in[4];
    const float* c3w   = (const float*)d_in[5];
    const float* c3b   = (const float*)d_in[6];
    const float* l5w   = (const float*)d_in[7];
    const float* l5b   = (const float*)d_in[8];
    const float* l4w   = (const float*)d_in[9];
    const float* l4b   = (const float*)d_in[10];
    const float* l3w   = (const float*)d_in[11];
    const float* l3b   = (const float*)d_in[12];
    const float* fw    = (const float*)d_in[13];
    const float* fb    = (const float*)d_in[14];
    float* out = (float*)d_out;

    const int NCONV = BATCH * 4 / 4;   // 8192 CTAs
    const int sh5 = (4 * (25 * NC + 4) + 2 * 4896) * 4;   // 66432 B
    const int sh4 = (4 * (16 * NC + 4) + 2 * 4896) * 4;   // 56640 B
    const int sh3 = (4 * ( 9 * NC + 4) + 2 * 4896) * 4;   // 49024 B

    // >48KB dynamic smem requires explicit opt-in (host-side call, capture-safe)
    cudaFuncSetAttribute(conv_pipe<5, true >, cudaFuncAttributeMaxDynamicSharedMemorySize, sh5);
    cudaFuncSetAttribute(conv_pipe<4, false>, cudaFuncAttributeMaxDynamicSharedMemorySize, sh4);
    cudaFuncSetAttribute(conv_pipe<3, false>, cudaFuncAttributeMaxDynamicSharedMemorySize, sh3);

    prep_w<<<(2 * 9 * 4896 + 255) / 256, 256>>>(c1w, c3w);

    // ws = 5
    conv_pipe<5, true ><<<NCONV, 272, sh5>>>(x, cell, coord, c1b, c3b);
    sgemm2<0><<<dim3(5, 256), 256>>>(l5w, l5b, NC * 25, 576);
    // ws = 4
    conv_pipe<4, false><<<NCONV, 272, sh4>>>(x, cell, coord, c1b, c3b);
    sgemm2<0><<<dim3(5, 256), 256>>>(l4w, l4b, NC * 16, 576);
    // ws = 3
    conv_pipe<3, false><<<NCONV, 272, sh3>>>(x, cell, coord, c1b, c3b);
    sgemm2<0><<<dim3(5, 256), 256>>>(l3w, l3b, NC * 9, 576);
    // final
    extract_final_kernel<<<(4 * BATCH * 576 + 255) / 256, 256>>>();
    sgemm2<1><<<dim3(1, 256), 256>>>(fw, fb, 576, NHS);
    final_mul_kernel<<<(BATCH * NHS * 4 + 255) / 256, 256>>>(out);
}